// round 7
// baseline (speedup 1.0000x reference)
#include <cuda_runtime.h>
#include <cuda_bf16.h>
#include <cstdint>

// ---------------- problem dims ----------------
#define BB 64
#define TT 512
#define II 128
#define NN 2048
#define NTILES 16
#define KSP 9                // 8 recurrent k-slices of 256 + 1 input slice
#define KSLICE 256
#define GRID (NTILES * KSP)  // 144 CTAs, co-resident (1 per SM)
#define NTHREADS 256

// ---------------- smem layout (bytes) ----------------
#define A_STRIDE 528
#define B_STRIDE 144
#define A_HI 0
#define A_LO (128 * A_STRIDE)
#define B_HI (2 * 128 * A_STRIDE)          // 135168
#define B_LO (B_HI + 256 * B_STRIDE)       // 172032
#define SMEM_DYN (B_LO + 256 * B_STRIDE)   // 208896
// out staging aliased onto (dead) B region: float[64][132] = 33792 B

// ---------------- device globals ----------------
__device__ float g_h[2][NN * BB];                // hidden state ping-pong, [n][b]
__device__ float g_partial[2][KSP][NN * BB];     // split-K partials, ping-pong
__device__ __nv_bfloat16 g_rhi[2][NN * BB];      // relu(h) hi ping-pong, [n][b]
__device__ __nv_bfloat16 g_rlo[2][NN * BB];
__device__ __nv_bfloat16 g_xhi[TT * II * BB];    // x hi, [t][i][b]
__device__ __nv_bfloat16 g_xlo[TT * II * BB];
// [0:16) P[nt], [16:32) RDY[nt], [32] arrive
__device__ unsigned int g_sync[64];
#define P_CNT  (&g_sync[0])
#define RDY    (&g_sync[16])
#define ARRIVE (&g_sync[32])

// ---------------- helpers ----------------
__device__ __forceinline__ uint32_t smem_u32(const void* p) {
    uint32_t a;
    asm("{ .reg .u64 t; cvta.to.shared.u64 t, %1; cvt.u32.u64 %0, t; }" : "=r"(a) : "l"(p));
    return a;
}
__device__ __forceinline__ void ldsm4(uint32_t* r, uint32_t addr) {
    asm volatile("ldmatrix.sync.aligned.m8n8.x4.shared.b16 {%0,%1,%2,%3}, [%4];"
                 : "=r"(r[0]), "=r"(r[1]), "=r"(r[2]), "=r"(r[3]) : "r"(addr));
}
__device__ __forceinline__ void ldsm4t(uint32_t* r, uint32_t addr) {
    asm volatile("ldmatrix.sync.aligned.m8n8.x4.trans.shared.b16 {%0,%1,%2,%3}, [%4];"
                 : "=r"(r[0]), "=r"(r[1]), "=r"(r[2]), "=r"(r[3]) : "r"(addr));
}
__device__ __forceinline__ void mma16816(float* d, const uint32_t* a, const uint32_t* b) {
    asm volatile(
        "mma.sync.aligned.m16n8k16.row.col.f32.bf16.bf16.f32 "
        "{%0,%1,%2,%3}, {%4,%5,%6,%7}, {%8,%9}, {%0,%1,%2,%3};"
        : "+f"(d[0]), "+f"(d[1]), "+f"(d[2]), "+f"(d[3])
        : "r"(a[0]), "r"(a[1]), "r"(a[2]), "r"(a[3]), "r"(b[0]), "r"(b[1]));
}
__device__ __forceinline__ void sig_add(unsigned int* p, unsigned int v) {
    asm volatile("red.release.gpu.global.add.u32 [%0], %1;" :: "l"(p), "r"(v) : "memory");
}
__device__ __forceinline__ unsigned int atom_add_acqrel(unsigned int* p, unsigned int v) {
    unsigned int old;
    asm volatile("atom.acq_rel.gpu.global.add.u32 %0, [%1], %2;"
                 : "=r"(old) : "l"(p), "r"(v) : "memory");
    return old;
}
__device__ __forceinline__ unsigned int ld_acq(const unsigned int* p) {
    unsigned int v;
    asm volatile("ld.acquire.gpu.global.u32 %0, [%1];" : "=r"(v) : "l"(p) : "memory");
    return v;
}
__device__ __forceinline__ void poll_ge(const unsigned int* p, unsigned int tgt) {
    while (ld_acq(p) < tgt) { __nanosleep(32); }
}
__device__ __forceinline__ void grid_barrier_once(unsigned int target) {
    __threadfence();
    __syncthreads();
    if (threadIdx.x == 0) {
        atomicAdd(ARRIVE, 1u);
        while (*(volatile unsigned int*)ARRIVE < target) { __nanosleep(64); }
        __threadfence();
    }
    __syncthreads();
}
__device__ __forceinline__ void load_frags(uint32_t aBase, uint32_t bBase, int kk,
                                           uint32_t* ahi, uint32_t* alo,
                                           uint32_t (*bhi)[2], uint32_t (*blo)[2]) {
    const uint32_t aA = aBase + (uint32_t)kk * 32;
    ldsm4(ahi, aA);
    ldsm4(alo, aA + (A_LO - A_HI));
    const uint32_t bA = bBase + (uint32_t)kk * 16 * B_STRIDE;
#pragma unroll
    for (int p = 0; p < 4; ++p) {
        ldsm4t(&bhi[2 * p][0], bA + p * 32);
        ldsm4t(&blo[2 * p][0], bA + p * 32 + (B_LO - B_HI));
    }
}
__device__ __forceinline__ void ldg_chunk(const char* srcHi, const char* srcLo,
                                          int c, int tid, uint4* vh, uint4* vl) {
#pragma unroll
    for (int q = 0; q < 2; ++q) {
        int s = 2 * tid + q;
        int lr = s >> 3, c16 = (s & 7) * 16;
        int off = (c * 64 + lr) * 128 + c16;
        vh[q] = __ldcg((const uint4*)(srcHi + off));
        vl[q] = __ldcg((const uint4*)(srcLo + off));
    }
}
__device__ __forceinline__ void sts_chunk(char* sm, int c, int tid,
                                          const uint4* vh, const uint4* vl) {
#pragma unroll
    for (int q = 0; q < 2; ++q) {
        int s = 2 * tid + q;
        int lr = s >> 3, c16 = (s & 7) * 16;
        *(uint4*)(sm + B_HI + (c * 64 + lr) * B_STRIDE + c16) = vh[q];
        *(uint4*)(sm + B_LO + (c * 64 + lr) * B_STRIDE + c16) = vl[q];
    }
}

// ---------------- persistent RNN kernel ----------------
__global__ void __launch_bounds__(NTHREADS, 1) rnn_persistent(
    const float* __restrict__ x,      // [B,T,I]
    const float* __restrict__ h0,     // [B,N]
    const float* __restrict__ Wrec,   // [N,N]
    const float* __restrict__ Winp,   // [N,I]
    const float* __restrict__ tonic,  // [N]
    const int*   __restrict__ mask,   // [N,N]
    const int*   __restrict__ sgn,    // [N,N]
    float* __restrict__ out)          // [B,T,N]
{
    extern __shared__ __align__(16) char sm[];
    const uint32_t smb = smem_u32(sm);
    __shared__ int s_red;

    const int cta = blockIdx.x;
    const int nt  = cta % NTILES;
    const int ks  = cta / NTILES;
    const int n0  = nt * 128;
    const int k0  = ks * KSLICE;
    const int tid = threadIdx.x;
    const int wid = tid >> 5;
    const int lane = tid & 31;
    const bool inp = (ks == KSP - 1);
    const int NCH = inp ? 2 : 4;          // 64-row chunks

    // ======== prologue (once per launch) ========
    for (int idx = tid; idx < 128 * 256; idx += NTHREADS) {
        int m = idx >> 8, c = idx & 255;
        int n = n0 + m;
        float v = 0.0f;
        if (!inp) {
            int k = k0 + c;
            float w = Wrec[n * NN + k];
            int ms = mask[n * NN + k] * sgn[n * NN + k];
            v = fmaxf(w, 0.0f) * (float)ms;
        } else if (c < II) {
            v = Winp[n * II + c];
        }
        __nv_bfloat16 hi = __float2bfloat16(v);
        __nv_bfloat16 lo = __float2bfloat16(v - __bfloat162float(hi));
        *(__nv_bfloat16*)(sm + A_HI + m * A_STRIDE + c * 2) = hi;
        *(__nv_bfloat16*)(sm + A_LO + m * A_STRIDE + c * 2) = lo;
    }
    {
        int gid = cta * NTHREADS + tid;
        if (gid < (NN * BB) / 4) {
            int base = gid * 4;
            int n = base >> 6, b0 = base & 63;
            float hv[4];
#pragma unroll
            for (int u = 0; u < 4; ++u) hv[u] = h0[(size_t)(b0 + u) * NN + n];
            *(float4*)&g_h[0][base] = make_float4(hv[0], hv[1], hv[2], hv[3]);
            __nv_bfloat16 hi4[4], lo4[4];
#pragma unroll
            for (int u = 0; u < 4; ++u) {
                float r = fmaxf(hv[u], 0.0f);
                hi4[u] = __float2bfloat16(r);
                lo4[u] = __float2bfloat16(r - __bfloat162float(hi4[u]));
            }
            *(uint2*)&g_rhi[0][base] = *(uint2*)hi4;
            *(uint2*)&g_rlo[0][base] = *(uint2*)lo4;
        }
    }
    for (int gid = cta * NTHREADS + tid; gid < (TT * II * BB) / 4; gid += GRID * NTHREADS) {
        int base = gid * 4;
        int b0 = base & 63;
        int i  = (base >> 6) & (II - 1);
        int t  = base >> 13;
        __nv_bfloat16 hi4[4], lo4[4];
#pragma unroll
        for (int u = 0; u < 4; ++u) {
            float v = __ldg(&x[((size_t)(b0 + u) * TT + t) * II + i]);
            hi4[u] = __float2bfloat16(v);
            lo4[u] = __float2bfloat16(v - __bfloat162float(hi4[u]));
        }
        *(uint2*)&g_xhi[base] = *(uint2*)hi4;
        *(uint2*)&g_xlo[base] = *(uint2*)lo4;
    }

    grid_barrier_once(GRID);

    const uint32_t aBase = smb + A_HI + (uint32_t)(wid * 16 + (lane & 15)) * A_STRIDE
                           + (uint32_t)(lane >> 4) * 16;
    const uint32_t bBase = smb + B_HI
                           + (uint32_t)((lane & 7) + ((lane >> 3) & 1) * 8) * B_STRIDE
                           + (uint32_t)(lane >> 4) * 16;

    const float AC = 0.1f, OMA = 0.9f;

    for (int t = 0; t < TT; ++t) {
        const int par = t & 1;

        __syncthreads();   // protect smem (out staging / B region) across iterations

        // ---- gate B-copy: r(t) rows for my slice ready ----
        if (!inp && t > 0) {
            if (tid == 0) {
                poll_ge(RDY + 2 * ks, (unsigned)t);
                poll_ge(RDY + 2 * ks + 1, (unsigned)t);
            }
            __syncthreads();
        }

        const char* srcHi = inp ? (const char*)&g_xhi[(size_t)t * II * BB]
                                : (const char*)&g_rhi[par][(size_t)k0 * BB];
        const char* srcLo = inp ? (const char*)&g_xlo[(size_t)t * II * BB]
                                : (const char*)&g_rlo[par][(size_t)k0 * BB];

        // ---- chunked B-copy overlapped with MMA ----
        float acc[8][4];
#pragma unroll
        for (int j = 0; j < 8; ++j)
#pragma unroll
            for (int q = 0; q < 4; ++q) acc[j][q] = 0.0f;

        uint4 vh[2], vl[2];
        ldg_chunk(srcHi, srcLo, 0, tid, vh, vl);

        uint32_t ahi[2][4], alo[2][4], bhi[2][8][2], blo[2][8][2];

        for (int c = 0; c < NCH; ++c) {
            sts_chunk(sm, c, tid, vh, vl);
            __syncthreads();
            if (c + 1 < NCH) ldg_chunk(srcHi, srcLo, c + 1, tid, vh, vl);

            load_frags(aBase, bBase, 4 * c, ahi[0], alo[0], bhi[0], blo[0]);
#pragma unroll
            for (int j = 0; j < 4; ++j) {
                const int cb = j & 1;
                if (j < 3)
                    load_frags(aBase, bBase, 4 * c + j + 1, ahi[cb ^ 1], alo[cb ^ 1],
                               bhi[cb ^ 1], blo[cb ^ 1]);
#pragma unroll
                for (int nb = 0; nb < 8; ++nb) {
                    mma16816(acc[nb], ahi[cb], bhi[cb][nb]);
                    mma16816(acc[nb], ahi[cb], blo[cb][nb]);
                    mma16816(acc[nb], alo[cb], bhi[cb][nb]);
                }
            }
        }

        // ---- gate partial store: my tile's reducer of iter t-1 done ----
        if (t > 0) {
            if (tid == 0) poll_ge(RDY + nt, (unsigned)t);
            __syncthreads();
        }
        {
            float* dst = &g_partial[par][ks][0];
            const int gi = lane >> 2;
            const int ti = lane & 3;
            const int r0 = n0 + wid * 16 + gi;
#pragma unroll
            for (int nb = 0; nb < 8; ++nb) {
                int cb2 = nb * 8 + 2 * ti;
                __stcg((float2*)&dst[(size_t)r0 * BB + cb2],
                       make_float2(acc[nb][0], acc[nb][1]));
                __stcg((float2*)&dst[(size_t)(r0 + 8) * BB + cb2],
                       make_float2(acc[nb][2], acc[nb][3]));
            }
        }
        __syncthreads();
        if (tid == 0) {
            unsigned old = atom_add_acqrel(P_CNT + nt, 1u);
            s_red = (old == 9u * (unsigned)t + 8u) ? 1 : 0;
        }
        __syncthreads();

        // ---- last producer reduces its tile ----
        if (s_red) {
            const float* __restrict__ curh = g_h[par];
            float* __restrict__ nxth = g_h[par ^ 1];
            __nv_bfloat16* __restrict__ rh = g_rhi[par ^ 1];
            __nv_bfloat16* __restrict__ rl = g_rlo[par ^ 1];
            float* smo = (float*)(sm + B_HI);   // [64][132] staging

#pragma unroll 2
            for (int u = tid; u < 128 * 16; u += NTHREADS) {
                int row = u >> 4;
                int b0 = (u & 15) * 4;
                size_t off = (size_t)(n0 + row) * BB + b0;
                float4 s = make_float4(0.f, 0.f, 0.f, 0.f);
#pragma unroll
                for (int p = 0; p < KSP; ++p) {
                    float4 q = __ldcg((const float4*)&g_partial[par][p][off]);
                    s.x += q.x; s.y += q.y; s.z += q.z; s.w += q.w;
                }
                float tn = __ldg(&tonic[n0 + row]);
                float4 hv = __ldcg((const float4*)&curh[off]);
                float4 r4;
                r4.x = OMA * hv.x + AC * (s.x + tn);
                r4.y = OMA * hv.y + AC * (s.y + tn);
                r4.z = OMA * hv.z + AC * (s.z + tn);
                r4.w = OMA * hv.w + AC * (s.w + tn);
                __stcg((float4*)&nxth[off], r4);

                float rr[4] = {fmaxf(r4.x, 0.f), fmaxf(r4.y, 0.f),
                               fmaxf(r4.z, 0.f), fmaxf(r4.w, 0.f)};
                __nv_bfloat16 hi4[4], lo4[4];
#pragma unroll
                for (int v = 0; v < 4; ++v) {
                    hi4[v] = __float2bfloat16(rr[v]);
                    lo4[v] = __float2bfloat16(rr[v] - __bfloat162float(hi4[v]));
                    smo[(b0 + v) * 132 + row] = rr[v];
                }
                *(uint2*)&rh[off] = *(uint2*)hi4;
                *(uint2*)&rl[off] = *(uint2*)lo4;
            }
            __syncthreads();
            if (tid == 0) sig_add(RDY + nt, 1u);

            // out writes off the critical path
            for (int idx = tid; idx < 64 * 32; idx += NTHREADS) {
                int b = idx >> 5;
                int q4 = (idx & 31) * 4;
                float4 v = *(float4*)&smo[b * 132 + q4];
                *(float4*)&out[((size_t)b * TT + t) * NN + n0 + q4] = v;
            }
        }
    }
}

// ---------------- launch ----------------
extern "C" void kernel_launch(void* const* d_in, const int* in_sizes, int n_in,
                              void* d_out, int out_size) {
    const float* x     = (const float*)d_in[0];
    const float* h0    = (const float*)d_in[1];
    const float* Wrec  = (const float*)d_in[2];
    const float* Winp  = (const float*)d_in[3];
    const float* tonic = (const float*)d_in[4];
    const int*   mask  = (const int*)d_in[5];
    const int*   sgn   = (const int*)d_in[6];
    float* out = (float*)d_out;

    cudaFuncSetAttribute(rnn_persistent,
                         cudaFuncAttributeMaxDynamicSharedMemorySize, SMEM_DYN);

    void* pa = nullptr;
    cudaGetSymbolAddress(&pa, g_sync);
    cudaMemsetAsync(pa, 0, sizeof(unsigned int) * 64);

    rnn_persistent<<<GRID, NTHREADS, SMEM_DYN>>>(x, h0, Wrec, Winp, tonic,
                                                 mask, sgn, out);
}

// round 8
// speedup vs baseline: 1.3037x; 1.3037x over previous
#include <cuda_runtime.h>
#include <cuda_bf16.h>
#include <cstdint>

// ---------------- problem dims ----------------
#define BB 64
#define TT 512
#define II 128
#define NN 2048
#define NTILES 16
#define KSP 9                 // 8 recurrent k-slices of 256 + 1 input slice
#define KSLICE 256
#define NSL 18                // partial slices = KSP * 2 (wk halves)
#define GRID (NTILES * KSP)   // 144 CTAs, co-resident (1 per SM)
#define NTHREADS 256

// ---------------- smem layout (bytes) ----------------
#define A_STRIDE 528
#define B_STRIDE 144
#define A_HI 0
#define A_LO (128 * A_STRIDE)
#define B_HI (2 * 128 * A_STRIDE)          // 135168
#define B_LO (B_HI + 256 * B_STRIDE)       // 172032
#define SMEM_DYN (B_LO + 256 * B_STRIDE)   // 208896

// ---------------- device globals ----------------
__device__ float g_h[2][NN * BB];                // hidden state ping-pong, [n][b]
__device__ float g_partial[NSL][NN * BB];        // split-K partials
__device__ __nv_bfloat16 g_rhi[NN * BB];         // relu(h) hi, [n][b]
__device__ __nv_bfloat16 g_rlo[NN * BB];
__device__ __nv_bfloat16 g_xhi[TT * II * BB];    // x hi, [t][i][b]
__device__ __nv_bfloat16 g_xlo[TT * II * BB];
__device__ unsigned int g_arrive;

// ---------------- helpers ----------------
__device__ __forceinline__ uint32_t smem_u32(const void* p) {
    uint32_t a;
    asm("{ .reg .u64 t; cvta.to.shared.u64 t, %1; cvt.u32.u64 %0, t; }" : "=r"(a) : "l"(p));
    return a;
}
__device__ __forceinline__ void ldsm4(uint32_t* r, uint32_t addr) {
    asm volatile("ldmatrix.sync.aligned.m8n8.x4.shared.b16 {%0,%1,%2,%3}, [%4];"
                 : "=r"(r[0]), "=r"(r[1]), "=r"(r[2]), "=r"(r[3]) : "r"(addr));
}
__device__ __forceinline__ void ldsm4t(uint32_t* r, uint32_t addr) {
    asm volatile("ldmatrix.sync.aligned.m8n8.x4.trans.shared.b16 {%0,%1,%2,%3}, [%4];"
                 : "=r"(r[0]), "=r"(r[1]), "=r"(r[2]), "=r"(r[3]) : "r"(addr));
}
__device__ __forceinline__ void mma16816(float* d, const uint32_t* a, const uint32_t* b) {
    asm volatile(
        "mma.sync.aligned.m16n8k16.row.col.f32.bf16.bf16.f32 "
        "{%0,%1,%2,%3}, {%4,%5,%6,%7}, {%8,%9}, {%0,%1,%2,%3};"
        : "+f"(d[0]), "+f"(d[1]), "+f"(d[2]), "+f"(d[3])
        : "r"(a[0]), "r"(a[1]), "r"(a[2]), "r"(a[3]), "r"(b[0]), "r"(b[1]));
}
__device__ __forceinline__ void sig_add(unsigned int* p, unsigned int v) {
    asm volatile("red.release.gpu.global.add.u32 [%0], %1;" :: "l"(p), "r"(v) : "memory");
}
__device__ __forceinline__ unsigned int ld_acq(const unsigned int* p) {
    unsigned int v;
    asm volatile("ld.acquire.gpu.global.u32 %0, [%1];" : "=r"(v) : "l"(p) : "memory");
    return v;
}
__device__ __forceinline__ void poll_ge(const unsigned int* p, unsigned int tgt) {
    while (ld_acq(p) < tgt) { __nanosleep(32); }
}
__device__ __forceinline__ void cp16(uint32_t dst, const void* src) {
    asm volatile("cp.async.cg.shared.global [%0], [%1], 16;" :: "r"(dst), "l"(src) : "memory");
}
__device__ __forceinline__ void cp_wait_all() {
    asm volatile("cp.async.commit_group;" ::: "memory");
    asm volatile("cp.async.wait_group 0;" ::: "memory");
}
__device__ __forceinline__ void named_bar(int id) {
    asm volatile("bar.sync %0, 128;" :: "r"(id) : "memory");
}

// ---------------- persistent RNN kernel ----------------
__global__ void __launch_bounds__(NTHREADS, 1) rnn_persistent(
    const float* __restrict__ x,      // [B,T,I]
    const float* __restrict__ h0,     // [B,N]
    const float* __restrict__ Wrec,   // [N,N]
    const float* __restrict__ Winp,   // [N,I]
    const float* __restrict__ tonic,  // [N]
    const int*   __restrict__ mask,   // [N,N]
    const int*   __restrict__ sgn,    // [N,N]
    float* __restrict__ out)          // [B,T,N]
{
    extern __shared__ __align__(16) char sm[];
    const uint32_t smb = smem_u32(sm);
    __shared__ float sm_out[64][25];   // out staging [b][row], rows<=24

    const int cta = blockIdx.x;
    const int nt  = cta % NTILES;
    const int ks  = cta / NTILES;
    const int n0  = nt * 128;
    const int k0  = ks * KSLICE;
    const int tid = threadIdx.x;
    const int wid = tid >> 5;
    const int lane = tid & 31;
    const bool inp = (ks == KSP - 1);

    // warp grid: wk = wid>>2 (contiguous 128-thread groups), wm = wid&1, wb = (wid>>1)&1
    const int wk = wid >> 2;
    const int wm = wid & 1;
    const int wb = (wid >> 1) & 1;
    const int KS = inp ? 4 : 8;            // ksteps per warp (half K)
    const int kkbase = wk * KS;
    const int sp = ks * 2 + wk;            // partial slice id (0..17)

    // ======== prologue (once per launch) ========
    for (int idx = tid; idx < 128 * 256; idx += NTHREADS) {
        int m = idx >> 8, c = idx & 255;
        int n = n0 + m;
        float v = 0.0f;
        if (!inp) {
            int k = k0 + c;
            float w = Wrec[n * NN + k];
            int ms = mask[n * NN + k] * sgn[n * NN + k];
            v = fmaxf(w, 0.0f) * (float)ms;
        } else if (c < II) {
            v = Winp[n * II + c];
        }
        __nv_bfloat16 hi = __float2bfloat16(v);
        __nv_bfloat16 lo = __float2bfloat16(v - __bfloat162float(hi));
        *(__nv_bfloat16*)(sm + A_HI + m * A_STRIDE + c * 2) = hi;
        *(__nv_bfloat16*)(sm + A_LO + m * A_STRIDE + c * 2) = lo;
    }
    {
        int gid = cta * NTHREADS + tid;
        if (gid < (NN * BB) / 4) {
            int base = gid * 4;
            int n = base >> 6, b0 = base & 63;
            float hv[4];
#pragma unroll
            for (int u = 0; u < 4; ++u) hv[u] = h0[(size_t)(b0 + u) * NN + n];
            *(float4*)&g_h[0][base] = make_float4(hv[0], hv[1], hv[2], hv[3]);
            __nv_bfloat16 hi4[4], lo4[4];
#pragma unroll
            for (int u = 0; u < 4; ++u) {
                float r = fmaxf(hv[u], 0.0f);
                hi4[u] = __float2bfloat16(r);
                lo4[u] = __float2bfloat16(r - __bfloat162float(hi4[u]));
            }
            *(uint2*)&g_rhi[base] = *(uint2*)hi4;
            *(uint2*)&g_rlo[base] = *(uint2*)lo4;
        }
    }
    for (int gid = cta * NTHREADS + tid; gid < (TT * II * BB) / 4; gid += GRID * NTHREADS) {
        int base = gid * 4;
        int b0 = base & 63;
        int i  = (base >> 6) & (II - 1);
        int t  = base >> 13;
        __nv_bfloat16 hi4[4], lo4[4];
#pragma unroll
        for (int u = 0; u < 4; ++u) {
            float v = __ldg(&x[((size_t)(b0 + u) * TT + t) * II + i]);
            hi4[u] = __float2bfloat16(v);
            lo4[u] = __float2bfloat16(v - __bfloat162float(hi4[u]));
        }
        *(uint2*)&g_xhi[base] = *(uint2*)hi4;
        *(uint2*)&g_xlo[base] = *(uint2*)lo4;
    }

    // prologue barrier
    unsigned int bar = GRID;
    __threadfence();
    __syncthreads();
    if (tid == 0) { sig_add(&g_arrive, 1u); poll_ge(&g_arrive, bar); }
    __syncthreads();

    // fragment base addresses
    // A: warp rows = wm*64 + mt*16
    const uint32_t aBase = smb + A_HI
        + (uint32_t)(wm * 64 + (lane & 15)) * A_STRIDE + (uint32_t)(lane >> 4) * 16;
    // B: cols = wb*32 (byte offset wb*64 within row)
    const uint32_t bBase = smb + B_HI
        + (uint32_t)((lane & 7) + ((lane >> 3) & 1) * 8) * B_STRIDE
        + (uint32_t)(lane >> 4) * 16 + (uint32_t)wb * 64;

    // reduce ownership (rebalanced: input CTAs take more rows)
    const int Rrows = inp ? 24 : 13;
    const int nbase = inp ? (1664 + nt * 24) : (cta * 13);

    const float AC = 0.1f, OMA = 0.9f;
    const int wg_tid = tid & 127;          // thread within wk group

    for (int t = 0; t < TT; ++t) {
        const float* __restrict__ cur = g_h[t & 1];
        float* __restrict__ nxt = g_h[(t + 1) & 1];

        // ---- phase 1: per-half cp.async B-copy (each wk group copies its own rows) ----
        {
            const char* srcHi = inp ? (const char*)&g_xhi[(size_t)t * II * BB]
                                    : (const char*)&g_rhi[(size_t)k0 * BB];
            const char* srcLo = inp ? (const char*)&g_xlo[(size_t)t * II * BB]
                                    : (const char*)&g_rlo[(size_t)k0 * BB];
            const int half_rows = inp ? 64 : 128;    // rows per wk half
            const int row0 = wk * half_rows;
            const int nseg = half_rows * 8;          // 16B segs per plane
#pragma unroll 4
            for (int s = wg_tid; s < nseg; s += 128) {
                int r = row0 + (s >> 3), c16 = (s & 7) * 16;
                cp16(smb + B_HI + r * B_STRIDE + c16, srcHi + r * 128 + c16);
                cp16(smb + B_LO + r * B_STRIDE + c16, srcLo + r * 128 + c16);
            }
            cp_wait_all();
            named_bar(1 + wk);
        }

        // ---- phase 2: MMA on own k-half ----
        float acc[4][4][4];
#pragma unroll
        for (int a = 0; a < 4; ++a)
#pragma unroll
            for (int b = 0; b < 4; ++b)
#pragma unroll
                for (int q = 0; q < 4; ++q) acc[a][b][q] = 0.0f;

#pragma unroll 2
        for (int j = 0; j < KS; ++j) {
            const int kk = kkbase + j;
            uint32_t ahi[4][4], alo[4][4];
            const uint32_t aA = aBase + (uint32_t)kk * 32;
#pragma unroll
            for (int mt = 0; mt < 4; ++mt) {
                ldsm4(ahi[mt], aA + mt * 16 * A_STRIDE);
                ldsm4(alo[mt], aA + mt * 16 * A_STRIDE + (A_LO - A_HI));
            }
            uint32_t bhi[4][2], blo[4][2];
            const uint32_t bA = bBase + (uint32_t)kk * 16 * B_STRIDE;
            ldsm4t(&bhi[0][0], bA);
            ldsm4t(&bhi[2][0], bA + 32);
            ldsm4t(&blo[0][0], bA + (B_LO - B_HI));
            ldsm4t(&blo[2][0], bA + (B_LO - B_HI) + 32);
#pragma unroll
            for (int mt = 0; mt < 4; ++mt)
#pragma unroll
                for (int nb = 0; nb < 4; ++nb) {
                    mma16816(acc[mt][nb], ahi[mt], bhi[nb]);
                    mma16816(acc[mt][nb], ahi[mt], blo[nb]);
                    mma16816(acc[mt][nb], alo[mt], bhi[nb]);
                }
        }

        // ---- phase 3: store split-K partial (slice sp) ----
        {
            float* dst = &g_partial[sp][0];
            const int gi = lane >> 2;
            const int ti = lane & 3;
#pragma unroll
            for (int mt = 0; mt < 4; ++mt) {
                int r0 = n0 + wm * 64 + mt * 16 + gi;
#pragma unroll
                for (int nb = 0; nb < 4; ++nb) {
                    int cb = wb * 32 + nb * 8 + 2 * ti;
                    __stcg((float2*)&dst[(size_t)r0 * BB + cb],
                           make_float2(acc[mt][nb][0], acc[mt][nb][1]));
                    __stcg((float2*)&dst[(size_t)(r0 + 8) * BB + cb],
                           make_float2(acc[mt][nb][2], acc[mt][nb][3]));
                }
            }
        }

        // ---- barrier 1: partials visible ----
        bar += GRID;
        __syncthreads();
        if (tid == 0) { sig_add(&g_arrive, 1u); poll_ge(&g_arrive, bar); }
        __syncthreads();

        // ---- phase 4: distributed reduce + update + relu + publish r ----
        for (int u = tid; u < Rrows * 16; u += NTHREADS) {
            int row = u >> 4;
            int b0 = (u & 15) * 4;
            int n = nbase + row;
            size_t off = (size_t)n * BB + b0;

            float4 s = make_float4(0.f, 0.f, 0.f, 0.f);
#pragma unroll
            for (int p = 0; p < NSL; ++p) {
                float4 q = __ldcg((const float4*)&g_partial[p][off]);
                s.x += q.x; s.y += q.y; s.z += q.z; s.w += q.w;
            }
            float tn = __ldg(&tonic[n]);
            float4 hv = __ldcg((const float4*)&cur[off]);
            float4 r4;
            r4.x = OMA * hv.x + AC * (s.x + tn);
            r4.y = OMA * hv.y + AC * (s.y + tn);
            r4.z = OMA * hv.z + AC * (s.z + tn);
            r4.w = OMA * hv.w + AC * (s.w + tn);
            __stcg((float4*)&nxt[off], r4);

            float rr[4] = {fmaxf(r4.x, 0.f), fmaxf(r4.y, 0.f),
                           fmaxf(r4.z, 0.f), fmaxf(r4.w, 0.f)};
            __nv_bfloat16 hi4[4], lo4[4];
#pragma unroll
            for (int v = 0; v < 4; ++v) {
                hi4[v] = __float2bfloat16(rr[v]);
                lo4[v] = __float2bfloat16(rr[v] - __bfloat162float(hi4[v]));
                sm_out[b0 + v][row] = rr[v];
            }
            *(uint2*)&g_rhi[off] = *(uint2*)hi4;
            *(uint2*)&g_rlo[off] = *(uint2*)lo4;
        }

        // ---- barrier 2 with out-writes overlapped into the wait ----
        bar += GRID;
        __syncthreads();
        if (tid == 0) sig_add(&g_arrive, 1u);
        for (int idx = tid; idx < Rrows * 64; idx += NTHREADS) {
            int b = idx / Rrows;
            int rr2 = idx - b * Rrows;
            out[((size_t)b * TT + t) * NN + nbase + rr2] = sm_out[b][rr2];
        }
        if (tid == 0) poll_ge(&g_arrive, bar);
        __syncthreads();
    }
}

// ---------------- launch ----------------
extern "C" void kernel_launch(void* const* d_in, const int* in_sizes, int n_in,
                              void* d_out, int out_size) {
    const float* x     = (const float*)d_in[0];
    const float* h0    = (const float*)d_in[1];
    const float* Wrec  = (const float*)d_in[2];
    const float* Winp  = (const float*)d_in[3];
    const float* tonic = (const float*)d_in[4];
    const int*   mask  = (const int*)d_in[5];
    const int*   sgn   = (const int*)d_in[6];
    float* out = (float*)d_out;

    cudaFuncSetAttribute(rnn_persistent,
                         cudaFuncAttributeMaxDynamicSharedMemorySize, SMEM_DYN);

    void* pa = nullptr;
    cudaGetSymbolAddress(&pa, g_arrive);
    cudaMemsetAsync(pa, 0, sizeof(unsigned int));

    rnn_persistent<<<GRID, NTHREADS, SMEM_DYN>>>(x, h0, Wrec, Winp, tonic,
                                                 mask, sgn, out);
}

// round 10
// speedup vs baseline: 1.3414x; 1.0290x over previous
#include <cuda_runtime.h>
#include <cuda_bf16.h>
#include <cstdint>

// ---------------- problem dims ----------------
#define BB 64
#define TT 512
#define II 128
#define NN 2048
#define NTILES 16
#define KSP 9                 // 8 recurrent k-slices of 256 + 1 input slice
#define KSLICE 256
#define NSL 18                // partial slices = KSP * 2 (wk halves)
#define GRID (NTILES * KSP)   // 144 CTAs, co-resident (1 per SM)
#define NTHREADS 256

// ---------------- smem layout (bytes) ----------------
#define A_STRIDE 528
#define B_STRIDE 144
#define A_HI 0
#define A_LO (128 * A_STRIDE)
#define B_HI (2 * 128 * A_STRIDE)          // 135168
#define B_LO (B_HI + 256 * B_STRIDE)       // 172032
#define SMEM_DYN (B_LO + 256 * B_STRIDE)   // 208896

// ---------------- device globals ----------------
__device__ float g_h[2][NN * BB];                // hidden state ping-pong, [n][b]
__device__ float g_partial[NSL][NN * BB];        // split-K partials
__device__ __nv_bfloat16 g_rhi[NN * BB];         // relu(h) hi, [n][b]
__device__ __nv_bfloat16 g_rlo[NN * BB];
__device__ __nv_bfloat16 g_xhi[TT * II * BB];    // x hi, [t][i][b]
__device__ __nv_bfloat16 g_xlo[TT * II * BB];
__device__ unsigned int g_arrive;

// ---------------- helpers ----------------
__device__ __forceinline__ uint32_t smem_u32(const void* p) {
    uint32_t a;
    asm("{ .reg .u64 t; cvta.to.shared.u64 t, %1; cvt.u32.u64 %0, t; }" : "=r"(a) : "l"(p));
    return a;
}
__device__ __forceinline__ void ldsm4(uint32_t* r, uint32_t addr) {
    asm volatile("ldmatrix.sync.aligned.m8n8.x4.shared.b16 {%0,%1,%2,%3}, [%4];"
                 : "=r"(r[0]), "=r"(r[1]), "=r"(r[2]), "=r"(r[3]) : "r"(addr));
}
__device__ __forceinline__ void ldsm4t(uint32_t* r, uint32_t addr) {
    asm volatile("ldmatrix.sync.aligned.m8n8.x4.trans.shared.b16 {%0,%1,%2,%3}, [%4];"
                 : "=r"(r[0]), "=r"(r[1]), "=r"(r[2]), "=r"(r[3]) : "r"(addr));
}
__device__ __forceinline__ void mma16816(float* d, const uint32_t* a, const uint32_t* b) {
    asm volatile(
        "mma.sync.aligned.m16n8k16.row.col.f32.bf16.bf16.f32 "
        "{%0,%1,%2,%3}, {%4,%5,%6,%7}, {%8,%9}, {%0,%1,%2,%3};"
        : "+f"(d[0]), "+f"(d[1]), "+f"(d[2]), "+f"(d[3])
        : "r"(a[0]), "r"(a[1]), "r"(a[2]), "r"(a[3]), "r"(b[0]), "r"(b[1]));
}
__device__ __forceinline__ void sig_add(unsigned int* p, unsigned int v) {
    asm volatile("red.release.gpu.global.add.u32 [%0], %1;" :: "l"(p), "r"(v) : "memory");
}
__device__ __forceinline__ unsigned int ld_acq(const unsigned int* p) {
    unsigned int v;
    asm volatile("ld.acquire.gpu.global.u32 %0, [%1];" : "=r"(v) : "l"(p) : "memory");
    return v;
}
__device__ __forceinline__ void poll_ge(const unsigned int* p, unsigned int tgt) {
    while (ld_acq(p) < tgt) { __nanosleep(32); }
}
__device__ __forceinline__ void cp16(uint32_t dst, const void* src) {
    asm volatile("cp.async.cg.shared.global [%0], [%1], 16;" :: "r"(dst), "l"(src) : "memory");
}
__device__ __forceinline__ void cp_commit() {
    asm volatile("cp.async.commit_group;" ::: "memory");
}
__device__ __forceinline__ void cp_waitg0() {
    asm volatile("cp.async.wait_group 0;" ::: "memory");
}
__device__ __forceinline__ void cp_waitg1() {
    asm volatile("cp.async.wait_group 1;" ::: "memory");
}
__device__ __forceinline__ void named_bar(int id) {
    asm volatile("bar.sync %0, 128;" :: "r"(id) : "memory");
}

// ---------------- persistent RNN kernel ----------------
__global__ void __launch_bounds__(NTHREADS, 1) rnn_persistent(
    const float* __restrict__ x,      // [B,T,I]
    const float* __restrict__ h0,     // [B,N]
    const float* __restrict__ Wrec,   // [N,N]
    const float* __restrict__ Winp,   // [N,I]
    const float* __restrict__ tonic,  // [N]
    const int*   __restrict__ mask,   // [N,N]
    const int*   __restrict__ sgn,    // [N,N]
    float* __restrict__ out)          // [B,T,N]
{
    extern __shared__ __align__(16) char sm[];
    const uint32_t smb = smem_u32(sm);
    __shared__ float sm_out[64][25];   // out staging [b][row], rows<=24

    const int cta = blockIdx.x;
    const int nt  = cta % NTILES;
    const int ks  = cta / NTILES;
    const int n0  = nt * 128;
    const int k0  = ks * KSLICE;
    const int tid = threadIdx.x;
    const int wid = tid >> 5;
    const int lane = tid & 31;
    const int wg_tid = tid & 127;
    const bool inp = (ks == KSP - 1);

    // warp grid: wk = wid>>2, wm = wid&1, wb = (wid>>1)&1
    const int wk = wid >> 2;
    const int wm = wid & 1;
    const int wb = (wid >> 1) & 1;
    const int KS = inp ? 4 : 8;            // ksteps per warp (half K)
    const int KH = KS >> 1;                // ksteps per chunk
    const int kkbase = wk * KS;
    const int sp = ks * 2 + wk;            // partial slice id (0..17)

    // ======== prologue (once per launch) ========
    for (int idx = tid; idx < 128 * 256; idx += NTHREADS) {
        int m = idx >> 8, c = idx & 255;
        int n = n0 + m;
        float v = 0.0f;
        if (!inp) {
            int k = k0 + c;
            float w = Wrec[(size_t)n * NN + k];
            int ms = mask[(size_t)n * NN + k] * sgn[(size_t)n * NN + k];
            v = fmaxf(w, 0.0f) * (float)ms;
        } else if (c < II) {
            v = Winp[(size_t)n * II + c];
        }
        __nv_bfloat16 hi = __float2bfloat16(v);
        __nv_bfloat16 lo = __float2bfloat16(v - __bfloat162float(hi));
        *(__nv_bfloat16*)(sm + A_HI + m * A_STRIDE + c * 2) = hi;
        *(__nv_bfloat16*)(sm + A_LO + m * A_STRIDE + c * 2) = lo;
    }
    {
        int gid = cta * NTHREADS + tid;
        if (gid < (NN * BB) / 4) {
            int base = gid * 4;
            int n = base >> 6, b0 = base & 63;
            float hv[4];
#pragma unroll
            for (int u = 0; u < 4; ++u) hv[u] = h0[(size_t)(b0 + u) * NN + n];
            *(float4*)&g_h[0][base] = make_float4(hv[0], hv[1], hv[2], hv[3]);
            __nv_bfloat16 hi4[4], lo4[4];
#pragma unroll
            for (int u = 0; u < 4; ++u) {
                float r = fmaxf(hv[u], 0.0f);
                hi4[u] = __float2bfloat16(r);
                lo4[u] = __float2bfloat16(r - __bfloat162float(hi4[u]));
            }
            *(uint2*)&g_rhi[base] = *(uint2*)hi4;
            *(uint2*)&g_rlo[base] = *(uint2*)lo4;
        }
    }
    for (int gid = cta * NTHREADS + tid; gid < (TT * II * BB) / 4; gid += GRID * NTHREADS) {
        int base = gid * 4;
        int b0 = base & 63;
        int i  = (base >> 6) & (II - 1);
        int t  = base >> 13;
        __nv_bfloat16 hi4[4], lo4[4];
#pragma unroll
        for (int u = 0; u < 4; ++u) {
            float v = __ldg(&x[((size_t)(b0 + u) * TT + t) * II + i]);
            hi4[u] = __float2bfloat16(v);
            lo4[u] = __float2bfloat16(v - __bfloat162float(hi4[u]));
        }
        *(uint2*)&g_xhi[base] = *(uint2*)hi4;
        *(uint2*)&g_xlo[base] = *(uint2*)lo4;
    }

    // prologue barrier
    unsigned int bar = GRID;
    __threadfence();
    __syncthreads();
    if (tid == 0) { sig_add(&g_arrive, 1u); poll_ge(&g_arrive, bar); }
    __syncthreads();

    // fragment base addresses
    const uint32_t aBase = smb + A_HI
        + (uint32_t)(wm * 64 + (lane & 15)) * A_STRIDE + (uint32_t)(lane >> 4) * 16;
    const uint32_t bBase = smb + B_HI
        + (uint32_t)((lane & 7) + ((lane >> 3) & 1) * 8) * B_STRIDE
        + (uint32_t)(lane >> 4) * 16 + (uint32_t)wb * 64;

    // reduce ownership (input CTAs take more rows)
    const int Rrows = inp ? 24 : 13;
    const int nbase = inp ? (1664 + nt * 24) : (cta * 13);

    const float AC = 0.1f, OMA = 0.9f;

    for (int t = 0; t < TT; ++t) {
        const float* __restrict__ cur = g_h[t & 1];
        float* __restrict__ nxt = g_h[(t + 1) & 1];

        // ---- phase 1: B-copy in 2 committed chunks (per wk half) ----
        const char* srcHi = inp ? (const char*)&g_xhi[(size_t)t * II * BB]
                                : (const char*)&g_rhi[(size_t)k0 * BB];
        const char* srcLo = inp ? (const char*)&g_xlo[(size_t)t * II * BB]
                                : (const char*)&g_rlo[(size_t)k0 * BB];
        const int half_rows = inp ? 64 : 128;   // rows per wk half
        const int crows = half_rows >> 1;       // rows per chunk
        const int row0 = wk * half_rows;
#pragma unroll
        for (int ch = 0; ch < 2; ++ch) {
            const int r0c = row0 + ch * crows;
            for (int s = wg_tid; s < crows * 8; s += 128) {
                int r = r0c + (s >> 3), c16 = (s & 7) * 16;
                cp16(smb + B_HI + r * B_STRIDE + c16, srcHi + r * 128 + c16);
                cp16(smb + B_LO + r * B_STRIDE + c16, srcLo + r * 128 + c16);
            }
            cp_commit();
        }

        // ---- phase 2: MMA, chunk 0 overlapped with chunk-1 arrival ----
        float acc[4][4][4];
#pragma unroll
        for (int a = 0; a < 4; ++a)
#pragma unroll
            for (int b = 0; b < 4; ++b)
#pragma unroll
                for (int q = 0; q < 4; ++q) acc[a][b][q] = 0.0f;

        cp_waitg1();
        named_bar(1 + wk);

#pragma unroll
        for (int half = 0; half < 2; ++half) {
#pragma unroll 2
            for (int j = half * KH; j < half * KH + KH; ++j) {
                const int kk = kkbase + j;
                uint32_t ahi[4][4], alo[4][4];
                const uint32_t aA = aBase + (uint32_t)kk * 32;
#pragma unroll
                for (int mt = 0; mt < 4; ++mt) {
                    ldsm4(ahi[mt], aA + mt * 16 * A_STRIDE);
                    ldsm4(alo[mt], aA + mt * 16 * A_STRIDE + (A_LO - A_HI));
                }
                uint32_t bhi[4][2], blo[4][2];
                const uint32_t bA = bBase + (uint32_t)kk * 16 * B_STRIDE;
                ldsm4t(&bhi[0][0], bA);
                ldsm4t(&bhi[2][0], bA + 32);
                ldsm4t(&blo[0][0], bA + (B_LO - B_HI));
                ldsm4t(&blo[2][0], bA + (B_LO - B_HI) + 32);
#pragma unroll
                for (int mt = 0; mt < 4; ++mt)
#pragma unroll
                    for (int nb = 0; nb < 4; ++nb) {
                        mma16816(acc[mt][nb], ahi[mt], bhi[nb]);
                        mma16816(acc[mt][nb], ahi[mt], blo[nb]);
                        mma16816(acc[mt][nb], alo[mt], bhi[nb]);
                    }
            }
            if (half == 0) {
                cp_waitg0();
                named_bar(1 + wk);
            }
        }

        // ---- phase 3: store split-K partial (slice sp) ----
        {
            float* dst = &g_partial[sp][0];
            const int gi = lane >> 2;
            const int ti = lane & 3;
#pragma unroll
            for (int mt = 0; mt < 4; ++mt) {
                int r0 = n0 + wm * 64 + mt * 16 + gi;
#pragma unroll
                for (int nb = 0; nb < 4; ++nb) {
                    int cb = wb * 32 + nb * 8 + 2 * ti;
                    __stcg((float2*)&dst[(size_t)r0 * BB + cb],
                           make_float2(acc[mt][nb][0], acc[mt][nb][1]));
                    __stcg((float2*)&dst[(size_t)(r0 + 8) * BB + cb],
                           make_float2(acc[mt][nb][2], acc[mt][nb][3]));
                }
            }
        }

        // ---- barrier 1: partials visible ----
        bar += GRID;
        __syncthreads();
        if (tid == 0) { sig_add(&g_arrive, 1u); poll_ge(&g_arrive, bar); }
        __syncthreads();

        // ---- phase 4: distributed reduce + update + relu + publish r ----
        for (int u = tid; u < Rrows * 16; u += NTHREADS) {
            int row = u >> 4;
            int b0 = (u & 15) * 4;
            int n = nbase + row;
            size_t off = (size_t)n * BB + b0;

            float4 s = make_float4(0.f, 0.f, 0.f, 0.f);
#pragma unroll
            for (int p = 0; p < NSL; ++p) {
                float4 q = __ldcg((const float4*)&g_partial[p][off]);
                s.x += q.x; s.y += q.y; s.z += q.z; s.w += q.w;
            }
            float tn = __ldg(&tonic[n]);
            float4 hv = __ldcg((const float4*)&cur[off]);
            float4 r4;
            r4.x = OMA * hv.x + AC * (s.x + tn);
            r4.y = OMA * hv.y + AC * (s.y + tn);
            r4.z = OMA * hv.z + AC * (s.z + tn);
            r4.w = OMA * hv.w + AC * (s.w + tn);
            __stcg((float4*)&nxt[off], r4);

            float rr[4] = {fmaxf(r4.x, 0.f), fmaxf(r4.y, 0.f),
                           fmaxf(r4.z, 0.f), fmaxf(r4.w, 0.f)};
            __nv_bfloat16 hi4[4], lo4[4];
#pragma unroll
            for (int v = 0; v < 4; ++v) {
                hi4[v] = __float2bfloat16(rr[v]);
                lo4[v] = __float2bfloat16(rr[v] - __bfloat162float(hi4[v]));
                sm_out[b0 + v][row] = rr[v];
            }
            *(uint2*)&g_rhi[off] = *(uint2*)hi4;
            *(uint2*)&g_rlo[off] = *(uint2*)lo4;
        }

        // ---- barrier 2 with out-writes overlapped into the wait ----
        bar += GRID;
        __syncthreads();
        if (tid == 0) sig_add(&g_arrive, 1u);
        for (int idx = tid; idx < Rrows * 64; idx += NTHREADS) {
            int b = idx / Rrows;
            int rr2 = idx - b * Rrows;
            out[((size_t)b * TT + t) * NN + nbase + rr2] = sm_out[b][rr2];
        }
        if (tid == 0) poll_ge(&g_arrive, bar);
        __syncthreads();
    }
}

// ---------------- launch ----------------
extern "C" void kernel_launch(void* const* d_in, const int* in_sizes, int n_in,
                              void* d_out, int out_size) {
    const float* x     = (const float*)d_in[0];
    const float* h0    = (const float*)d_in[1];
    const float* Wrec  = (const float*)d_in[2];
    const float* Winp  = (const float*)d_in[3];
    const float* tonic = (const float*)d_in[4];
    const int*   mask  = (const int*)d_in[5];
    const int*   sgn   = (const int*)d_in[6];
    float* out = (float*)d_out;

    cudaFuncSetAttribute(rnn_persistent,
                         cudaFuncAttributeMaxDynamicSharedMemorySize, SMEM_DYN);

    void* pa = nullptr;
    cudaGetSymbolAddress(&pa, g_arrive);
    cudaMemsetAsync(pa, 0, sizeof(unsigned int));

    rnn_persistent<<<GRID, NTHREADS, SMEM_DYN>>>(x, h0, Wrec, Winp, tonic,
                                                 mask, sgn, out);
}

// round 11
// speedup vs baseline: 1.6213x; 1.2086x over previous
#include <cuda_runtime.h>
#include <cuda_fp16.h>
#include <cstdint>

// ---------------- problem dims ----------------
#define BB 64
#define TT 512
#define II 128
#define NN 2048
#define NTILES 16
#define KSP 9                 // 8 recurrent k-slices of 256 + 1 input slice
#define KSLICE 256
#define NSL 18                // partial slices = KSP * 2 (wk halves)
#define GRID (NTILES * KSP)   // 144 CTAs, co-resident (1 per SM)
#define NTHREADS 256

// ---------------- smem layout (bytes) ----------------
#define A_STRIDE 528                       // 256 fp16 + 16B pad
#define B_STRIDE 144                       // 64 fp16 + 16B pad
#define A_HI 0
#define A_LO (128 * A_STRIDE)              // 67584
#define B_OFF (2 * 128 * A_STRIDE)         // 135168
#define SMEM_DYN (B_OFF + 256 * B_STRIDE)  // 172032

// ---------------- device globals ----------------
__device__ float g_h[2][NN * BB];                // hidden state ping-pong, [n][b]
__device__ float g_partial[NSL][NN * BB];        // split-K partials
__device__ __half g_r16[NN * BB];                // relu(h) fp16, [n][b]
__device__ __half g_x16[TT * II * BB];           // x fp16, [t][i][b]
__device__ unsigned int g_arrive;

// ---------------- helpers ----------------
__device__ __forceinline__ uint32_t smem_u32(const void* p) {
    uint32_t a;
    asm("{ .reg .u64 t; cvta.to.shared.u64 t, %1; cvt.u32.u64 %0, t; }" : "=r"(a) : "l"(p));
    return a;
}
__device__ __forceinline__ void ldsm4(uint32_t* r, uint32_t addr) {
    asm volatile("ldmatrix.sync.aligned.m8n8.x4.shared.b16 {%0,%1,%2,%3}, [%4];"
                 : "=r"(r[0]), "=r"(r[1]), "=r"(r[2]), "=r"(r[3]) : "r"(addr));
}
__device__ __forceinline__ void ldsm4t(uint32_t* r, uint32_t addr) {
    asm volatile("ldmatrix.sync.aligned.m8n8.x4.trans.shared.b16 {%0,%1,%2,%3}, [%4];"
                 : "=r"(r[0]), "=r"(r[1]), "=r"(r[2]), "=r"(r[3]) : "r"(addr));
}
__device__ __forceinline__ void mma16816(float* d, const uint32_t* a, const uint32_t* b) {
    asm volatile(
        "mma.sync.aligned.m16n8k16.row.col.f32.f16.f16.f32 "
        "{%0,%1,%2,%3}, {%4,%5,%6,%7}, {%8,%9}, {%0,%1,%2,%3};"
        : "+f"(d[0]), "+f"(d[1]), "+f"(d[2]), "+f"(d[3])
        : "r"(a[0]), "r"(a[1]), "r"(a[2]), "r"(a[3]), "r"(b[0]), "r"(b[1]));
}
__device__ __forceinline__ void sig_add(unsigned int* p, unsigned int v) {
    asm volatile("red.release.gpu.global.add.u32 [%0], %1;" :: "l"(p), "r"(v) : "memory");
}
__device__ __forceinline__ unsigned int ld_acq(const unsigned int* p) {
    unsigned int v;
    asm volatile("ld.acquire.gpu.global.u32 %0, [%1];" : "=r"(v) : "l"(p) : "memory");
    return v;
}
__device__ __forceinline__ void poll_ge(const unsigned int* p, unsigned int tgt) {
    while (ld_acq(p) < tgt) { __nanosleep(32); }
}
__device__ __forceinline__ void cp16(uint32_t dst, const void* src) {
    asm volatile("cp.async.cg.shared.global [%0], [%1], 16;" :: "r"(dst), "l"(src) : "memory");
}
__device__ __forceinline__ void cp_commit() {
    asm volatile("cp.async.commit_group;" ::: "memory");
}
__device__ __forceinline__ void cp_waitg0() {
    asm volatile("cp.async.wait_group 0;" ::: "memory");
}
__device__ __forceinline__ void cp_waitg1() {
    asm volatile("cp.async.wait_group 1;" ::: "memory");
}
__device__ __forceinline__ void named_bar(int id) {
    asm volatile("bar.sync %0, 128;" :: "r"(id) : "memory");
}

// ---------------- persistent RNN kernel ----------------
__global__ void __launch_bounds__(NTHREADS, 1) rnn_persistent(
    const float* __restrict__ x,      // [B,T,I]
    const float* __restrict__ h0,     // [B,N]
    const float* __restrict__ Wrec,   // [N,N]
    const float* __restrict__ Winp,   // [N,I]
    const float* __restrict__ tonic,  // [N]
    const int*   __restrict__ mask,   // [N,N]
    const int*   __restrict__ sgn,    // [N,N]
    float* __restrict__ out)          // [B,T,N]
{
    extern __shared__ __align__(16) char sm[];
    const uint32_t smb = smem_u32(sm);
    __shared__ float sm_out[64][25];   // out staging [b][row], rows<=24

    const int cta = blockIdx.x;
    const int nt  = cta % NTILES;
    const int ks  = cta / NTILES;
    const int n0  = nt * 128;
    const int k0  = ks * KSLICE;
    const int tid = threadIdx.x;
    const int wid = tid >> 5;
    const int lane = tid & 31;
    const int wg_tid = tid & 127;
    const bool inp = (ks == KSP - 1);

    // warp grid: wk = wid>>2, wm = wid&1, wb = (wid>>1)&1
    const int wk = wid >> 2;
    const int wm = wid & 1;
    const int wb = (wid >> 1) & 1;
    const int KS = inp ? 4 : 8;            // ksteps per warp (half K)
    const int KH = KS >> 1;                // ksteps per chunk
    const int kkbase = wk * KS;
    const int sp = ks * 2 + wk;            // partial slice id (0..17)

    // ======== prologue (once per launch) ========
    // A (W slice) -> smem fp16 hi/lo
    for (int idx = tid; idx < 128 * 256; idx += NTHREADS) {
        int m = idx >> 8, c = idx & 255;
        int n = n0 + m;
        float v = 0.0f;
        if (!inp) {
            int k = k0 + c;
            float w = Wrec[(size_t)n * NN + k];
            int ms = mask[(size_t)n * NN + k] * sgn[(size_t)n * NN + k];
            v = fmaxf(w, 0.0f) * (float)ms;
        } else if (c < II) {
            v = Winp[(size_t)n * II + c];
        }
        __half hi = __float2half(v);
        __half lo = __float2half(v - __half2float(hi));
        *(__half*)(sm + A_HI + m * A_STRIDE + c * 2) = hi;
        *(__half*)(sm + A_LO + m * A_STRIDE + c * 2) = lo;
    }
    // h0 -> g_h[0] and g_r16 ([n][b] layout)
    {
        int gid = cta * NTHREADS + tid;
        if (gid < (NN * BB) / 4) {
            int base = gid * 4;
            int n = base >> 6, b0 = base & 63;
            float hv[4];
#pragma unroll
            for (int u = 0; u < 4; ++u) hv[u] = h0[(size_t)(b0 + u) * NN + n];
            *(float4*)&g_h[0][base] = make_float4(hv[0], hv[1], hv[2], hv[3]);
            __half2 r01 = __floats2half2_rn(fmaxf(hv[0], 0.f), fmaxf(hv[1], 0.f));
            __half2 r23 = __floats2half2_rn(fmaxf(hv[2], 0.f), fmaxf(hv[3], 0.f));
            uint2 pk;
            pk.x = *(uint32_t*)&r01;
            pk.y = *(uint32_t*)&r23;
            *(uint2*)&g_r16[base] = pk;
        }
    }
    // x -> g_x16 ([t][i][b] layout)
    for (int gid = cta * NTHREADS + tid; gid < (TT * II * BB) / 4; gid += GRID * NTHREADS) {
        int base = gid * 4;
        int b0 = base & 63;
        int i  = (base >> 6) & (II - 1);
        int t  = base >> 13;
        float v0 = __ldg(&x[((size_t)(b0 + 0) * TT + t) * II + i]);
        float v1 = __ldg(&x[((size_t)(b0 + 1) * TT + t) * II + i]);
        float v2 = __ldg(&x[((size_t)(b0 + 2) * TT + t) * II + i]);
        float v3 = __ldg(&x[((size_t)(b0 + 3) * TT + t) * II + i]);
        __half2 x01 = __floats2half2_rn(v0, v1);
        __half2 x23 = __floats2half2_rn(v2, v3);
        uint2 pk;
        pk.x = *(uint32_t*)&x01;
        pk.y = *(uint32_t*)&x23;
        *(uint2*)&g_x16[base] = pk;
    }

    // prologue barrier
    unsigned int bar = GRID;
    __threadfence();
    __syncthreads();
    if (tid == 0) { sig_add(&g_arrive, 1u); poll_ge(&g_arrive, bar); }
    __syncthreads();

    // fragment base addresses
    const uint32_t aBase = smb + A_HI
        + (uint32_t)(wm * 64 + (lane & 15)) * A_STRIDE + (uint32_t)(lane >> 4) * 16;
    const uint32_t bBase = smb + B_OFF
        + (uint32_t)((lane & 7) + ((lane >> 3) & 1) * 8) * B_STRIDE
        + (uint32_t)(lane >> 4) * 16 + (uint32_t)wb * 64;

    // reduce ownership (input CTAs take more rows)
    const int Rrows = inp ? 24 : 13;
    const int nbase = inp ? (1664 + nt * 24) : (cta * 13);

    const float AC = 0.1f, OMA = 0.9f;

    for (int t = 0; t < TT; ++t) {
        const float* __restrict__ cur = g_h[t & 1];
        float* __restrict__ nxt = g_h[(t + 1) & 1];

        // ---- phase 1: B-copy (single fp16 plane) in 2 committed chunks ----
        const char* src = inp ? (const char*)&g_x16[(size_t)t * II * BB]
                              : (const char*)&g_r16[(size_t)k0 * BB];
        const int half_rows = inp ? 64 : 128;   // rows per wk half
        const int crows = half_rows >> 1;       // rows per chunk
        const int row0 = wk * half_rows;
#pragma unroll
        for (int ch = 0; ch < 2; ++ch) {
            const int r0c = row0 + ch * crows;
            for (int s = wg_tid; s < crows * 8; s += 128) {
                int r = r0c + (s >> 3), c16 = (s & 7) * 16;
                cp16(smb + B_OFF + r * B_STRIDE + c16, src + r * 128 + c16);
            }
            cp_commit();
        }

        // ---- phase 2: 2-term fp16 MMA, chunk 0 overlapped with chunk-1 arrival ----
        float acc[4][4][4];
#pragma unroll
        for (int a = 0; a < 4; ++a)
#pragma unroll
            for (int b = 0; b < 4; ++b)
#pragma unroll
                for (int q = 0; q < 4; ++q) acc[a][b][q] = 0.0f;

        cp_waitg1();
        named_bar(1 + wk);

#pragma unroll
        for (int half = 0; half < 2; ++half) {
#pragma unroll 2
            for (int j = half * KH; j < half * KH + KH; ++j) {
                const int kk = kkbase + j;
                uint32_t ahi[4][4], alo[4][4];
                const uint32_t aA = aBase + (uint32_t)kk * 32;
#pragma unroll
                for (int mt = 0; mt < 4; ++mt) {
                    ldsm4(ahi[mt], aA + mt * 16 * A_STRIDE);
                    ldsm4(alo[mt], aA + mt * 16 * A_STRIDE + (A_LO - A_HI));
                }
                uint32_t bf[4][2];
                const uint32_t bA = bBase + (uint32_t)kk * 16 * B_STRIDE;
                ldsm4t(&bf[0][0], bA);
                ldsm4t(&bf[2][0], bA + 32);
#pragma unroll
                for (int mt = 0; mt < 4; ++mt)
#pragma unroll
                    for (int nb = 0; nb < 4; ++nb) {
                        mma16816(acc[mt][nb], ahi[mt], bf[nb]);
                        mma16816(acc[mt][nb], alo[mt], bf[nb]);
                    }
            }
            if (half == 0) {
                cp_waitg0();
                named_bar(1 + wk);
            }
        }

        // ---- phase 3: store split-K partial (slice sp) ----
        {
            float* dst = &g_partial[sp][0];
            const int gi = lane >> 2;
            const int ti = lane & 3;
#pragma unroll
            for (int mt = 0; mt < 4; ++mt) {
                int r0 = n0 + wm * 64 + mt * 16 + gi;
#pragma unroll
                for (int nb = 0; nb < 4; ++nb) {
                    int cb = wb * 32 + nb * 8 + 2 * ti;
                    __stcg((float2*)&dst[(size_t)r0 * BB + cb],
                           make_float2(acc[mt][nb][0], acc[mt][nb][1]));
                    __stcg((float2*)&dst[(size_t)(r0 + 8) * BB + cb],
                           make_float2(acc[mt][nb][2], acc[mt][nb][3]));
                }
            }
        }

        // ---- barrier 1: partials visible ----
        bar += GRID;
        __syncthreads();
        if (tid == 0) { sig_add(&g_arrive, 1u); poll_ge(&g_arrive, bar); }
        __syncthreads();

        // ---- phase 4: distributed reduce + update + relu + publish r ----
        for (int u = tid; u < Rrows * 16; u += NTHREADS) {
            int row = u >> 4;
            int b0 = (u & 15) * 4;
            int n = nbase + row;
            size_t off = (size_t)n * BB + b0;

            float4 s = make_float4(0.f, 0.f, 0.f, 0.f);
#pragma unroll
            for (int p = 0; p < NSL; ++p) {
                float4 q = __ldcg((const float4*)&g_partial[p][off]);
                s.x += q.x; s.y += q.y; s.z += q.z; s.w += q.w;
            }
            float tn = __ldg(&tonic[n]);
            float4 hv = __ldcg((const float4*)&cur[off]);
            float4 r4;
            r4.x = OMA * hv.x + AC * (s.x + tn);
            r4.y = OMA * hv.y + AC * (s.y + tn);
            r4.z = OMA * hv.z + AC * (s.z + tn);
            r4.w = OMA * hv.w + AC * (s.w + tn);
            __stcg((float4*)&nxt[off], r4);

            float rr[4] = {fmaxf(r4.x, 0.f), fmaxf(r4.y, 0.f),
                           fmaxf(r4.z, 0.f), fmaxf(r4.w, 0.f)};
            sm_out[b0 + 0][row] = rr[0];
            sm_out[b0 + 1][row] = rr[1];
            sm_out[b0 + 2][row] = rr[2];
            sm_out[b0 + 3][row] = rr[3];

            __half2 r01 = __floats2half2_rn(rr[0], rr[1]);
            __half2 r23 = __floats2half2_rn(rr[2], rr[3]);
            uint2 pk;
            pk.x = *(uint32_t*)&r01;
            pk.y = *(uint32_t*)&r23;
            *(uint2*)&g_r16[off] = pk;
        }

        // ---- barrier 2 with out-writes overlapped into the wait ----
        bar += GRID;
        __syncthreads();
        if (tid == 0) sig_add(&g_arrive, 1u);
        for (int idx = tid; idx < Rrows * 64; idx += NTHREADS) {
            int b = idx / Rrows;
            int rr2 = idx - b * Rrows;
            out[((size_t)b * TT + t) * NN + nbase + rr2] = sm_out[b][rr2];
        }
        if (tid == 0) poll_ge(&g_arrive, bar);
        __syncthreads();
    }
}

// ---------------- launch ----------------
extern "C" void kernel_launch(void* const* d_in, const int* in_sizes, int n_in,
                              void* d_out, int out_size) {
    const float* x     = (const float*)d_in[0];
    const float* h0    = (const float*)d_in[1];
    const float* Wrec  = (const float*)d_in[2];
    const float* Winp  = (const float*)d_in[3];
    const float* tonic = (const float*)d_in[4];
    const int*   mask  = (const int*)d_in[5];
    const int*   sgn   = (const int*)d_in[6];
    float* out = (float*)d_out;

    cudaFuncSetAttribute(rnn_persistent,
                         cudaFuncAttributeMaxDynamicSharedMemorySize, SMEM_DYN);

    void* pa = nullptr;
    cudaGetSymbolAddress(&pa, g_arrive);
    cudaMemsetAsync(pa, 0, sizeof(unsigned int));

    rnn_persistent<<<GRID, NTHREADS, SMEM_DYN>>>(x, h0, Wrec, Winp, tonic,
                                                 mask, sgn, out);
}

// round 12
// speedup vs baseline: 2.0130x; 1.2416x over previous
#include <cuda_runtime.h>
#include <cuda_fp16.h>
#include <cstdint>

// ---------------- problem dims ----------------
#define BB 64
#define TT 512
#define II 128
#define NN 2048
#define NTILES 16
#define KSP 9                 // 8 recurrent k-slices of 256 + 1 input slice
#define KSLICE 256
#define NSL 9                 // partial slices (wk pair pre-combined in CTA)
#define GRID (NTILES * KSP)   // 144 CTAs, co-resident (1 per SM)
#define NTHREADS 256

// ---------------- smem layout (bytes) ----------------
#define A_STRIDE 528                       // 256 fp16 + 16B pad
#define B_STRIDE 144                       // 64 fp16 + 16B pad
#define A_OFF 0
#define B_OFF (128 * A_STRIDE)             // 67584
#define SMEM_DYN (B_OFF + 256 * B_STRIDE)  // 104448
// exchange region aliases B after MMA: float[128][68] = 34816 B <= 36864

// ---------------- device globals ----------------
__device__ float g_h[2][NN * BB];                // hidden state ping-pong, [n][b]
__device__ float g_partial[NSL][NN * BB];        // split-K partials
__device__ __half g_r16[NN * BB];                // relu(h) fp16, [n][b]
__device__ __half g_x16[TT * II * BB];           // x fp16, [t][i][b]
__device__ unsigned int g_arrive;

// ---------------- helpers ----------------
__device__ __forceinline__ uint32_t smem_u32(const void* p) {
    uint32_t a;
    asm("{ .reg .u64 t; cvta.to.shared.u64 t, %1; cvt.u32.u64 %0, t; }" : "=r"(a) : "l"(p));
    return a;
}
__device__ __forceinline__ void ldsm4(uint32_t* r, uint32_t addr) {
    asm volatile("ldmatrix.sync.aligned.m8n8.x4.shared.b16 {%0,%1,%2,%3}, [%4];"
                 : "=r"(r[0]), "=r"(r[1]), "=r"(r[2]), "=r"(r[3]) : "r"(addr));
}
__device__ __forceinline__ void ldsm4t(uint32_t* r, uint32_t addr) {
    asm volatile("ldmatrix.sync.aligned.m8n8.x4.trans.shared.b16 {%0,%1,%2,%3}, [%4];"
                 : "=r"(r[0]), "=r"(r[1]), "=r"(r[2]), "=r"(r[3]) : "r"(addr));
}
__device__ __forceinline__ void mma16816(float* d, const uint32_t* a, const uint32_t* b) {
    asm volatile(
        "mma.sync.aligned.m16n8k16.row.col.f32.f16.f16.f32 "
        "{%0,%1,%2,%3}, {%4,%5,%6,%7}, {%8,%9}, {%0,%1,%2,%3};"
        : "+f"(d[0]), "+f"(d[1]), "+f"(d[2]), "+f"(d[3])
        : "r"(a[0]), "r"(a[1]), "r"(a[2]), "r"(a[3]), "r"(b[0]), "r"(b[1]));
}
__device__ __forceinline__ void sig_add(unsigned int* p, unsigned int v) {
    asm volatile("red.release.gpu.global.add.u32 [%0], %1;" :: "l"(p), "r"(v) : "memory");
}
__device__ __forceinline__ unsigned int ld_acq(const unsigned int* p) {
    unsigned int v;
    asm volatile("ld.acquire.gpu.global.u32 %0, [%1];" : "=r"(v) : "l"(p) : "memory");
    return v;
}
__device__ __forceinline__ void poll_ge(const unsigned int* p, unsigned int tgt) {
    while (ld_acq(p) < tgt) { __nanosleep(32); }
}
__device__ __forceinline__ void cp16(uint32_t dst, const void* src) {
    asm volatile("cp.async.cg.shared.global [%0], [%1], 16;" :: "r"(dst), "l"(src) : "memory");
}
__device__ __forceinline__ void cp_commit() {
    asm volatile("cp.async.commit_group;" ::: "memory");
}
__device__ __forceinline__ void cp_waitg0() {
    asm volatile("cp.async.wait_group 0;" ::: "memory");
}
__device__ __forceinline__ void cp_waitg1() {
    asm volatile("cp.async.wait_group 1;" ::: "memory");
}
__device__ __forceinline__ void named_bar(int id) {
    asm volatile("bar.sync %0, 128;" :: "r"(id) : "memory");
}

// ---------------- persistent RNN kernel ----------------
__global__ void __launch_bounds__(NTHREADS, 1) rnn_persistent(
    const float* __restrict__ x,      // [B,T,I]
    const float* __restrict__ h0,     // [B,N]
    const float* __restrict__ Wrec,   // [N,N]
    const float* __restrict__ Winp,   // [N,I]
    const float* __restrict__ tonic,  // [N]
    const int*   __restrict__ mask,   // [N,N]
    const int*   __restrict__ sgn,    // [N,N]
    float* __restrict__ out)          // [B,T,N]
{
    extern __shared__ __align__(16) char sm[];
    const uint32_t smb = smem_u32(sm);
    __shared__ float sm_out[64][25];   // out staging [b][row], rows<=24

    const int cta = blockIdx.x;
    const int nt  = cta % NTILES;
    const int ks  = cta / NTILES;
    const int n0  = nt * 128;
    const int k0  = ks * KSLICE;
    const int tid = threadIdx.x;
    const int wid = tid >> 5;
    const int lane = tid & 31;
    const int wg_tid = tid & 127;
    const bool inp = (ks == KSP - 1);

    // warp grid: wk = wid>>2, wm = wid&1, wb = (wid>>1)&1
    const int wk = wid >> 2;
    const int wm = wid & 1;
    const int wb = (wid >> 1) & 1;
    const int KS = inp ? 4 : 8;            // ksteps per warp (half K)
    const int KH = KS >> 1;                // ksteps per chunk
    const int kkbase = wk * KS;

    // ======== prologue (once per launch) ========
    // A (W slice) -> smem, single fp16 plane
    for (int idx = tid; idx < 128 * 256; idx += NTHREADS) {
        int m = idx >> 8, c = idx & 255;
        int n = n0 + m;
        float v = 0.0f;
        if (!inp) {
            int k = k0 + c;
            float w = Wrec[(size_t)n * NN + k];
            int ms = mask[(size_t)n * NN + k] * sgn[(size_t)n * NN + k];
            v = fmaxf(w, 0.0f) * (float)ms;
        } else if (c < II) {
            v = Winp[(size_t)n * II + c];
        }
        *(__half*)(sm + A_OFF + m * A_STRIDE + c * 2) = __float2half(v);
    }
    // h0 -> g_h[0] and g_r16 ([n][b] layout)
    {
        int gid = cta * NTHREADS + tid;
        if (gid < (NN * BB) / 4) {
            int base = gid * 4;
            int n = base >> 6, b0 = base & 63;
            float hv[4];
#pragma unroll
            for (int u = 0; u < 4; ++u) hv[u] = h0[(size_t)(b0 + u) * NN + n];
            *(float4*)&g_h[0][base] = make_float4(hv[0], hv[1], hv[2], hv[3]);
            __half2 r01 = __floats2half2_rn(fmaxf(hv[0], 0.f), fmaxf(hv[1], 0.f));
            __half2 r23 = __floats2half2_rn(fmaxf(hv[2], 0.f), fmaxf(hv[3], 0.f));
            uint2 pk;
            pk.x = *(uint32_t*)&r01;
            pk.y = *(uint32_t*)&r23;
            *(uint2*)&g_r16[base] = pk;
        }
    }
    // x -> g_x16 ([t][i][b] layout)
    for (int gid = cta * NTHREADS + tid; gid < (TT * II * BB) / 4; gid += GRID * NTHREADS) {
        int base = gid * 4;
        int b0 = base & 63;
        int i  = (base >> 6) & (II - 1);
        int t  = base >> 13;
        float v0 = __ldg(&x[((size_t)(b0 + 0) * TT + t) * II + i]);
        float v1 = __ldg(&x[((size_t)(b0 + 1) * TT + t) * II + i]);
        float v2 = __ldg(&x[((size_t)(b0 + 2) * TT + t) * II + i]);
        float v3 = __ldg(&x[((size_t)(b0 + 3) * TT + t) * II + i]);
        __half2 x01 = __floats2half2_rn(v0, v1);
        __half2 x23 = __floats2half2_rn(v2, v3);
        uint2 pk;
        pk.x = *(uint32_t*)&x01;
        pk.y = *(uint32_t*)&x23;
        *(uint2*)&g_x16[base] = pk;
    }

    // prologue barrier
    unsigned int bar = GRID;
    __threadfence();
    __syncthreads();
    if (tid == 0) { sig_add(&g_arrive, 1u); poll_ge(&g_arrive, bar); }
    __syncthreads();

    // fragment base addresses
    const uint32_t aBase = smb + A_OFF
        + (uint32_t)(wm * 64 + (lane & 15)) * A_STRIDE + (uint32_t)(lane >> 4) * 16;
    const uint32_t bBase = smb + B_OFF
        + (uint32_t)((lane & 7) + ((lane >> 3) & 1) * 8) * B_STRIDE
        + (uint32_t)(lane >> 4) * 16 + (uint32_t)wb * 64;

    // reduce ownership (input CTAs take more rows)
    const int Rrows = inp ? 24 : 13;
    const int nbase = inp ? (1664 + nt * 24) : (cta * 13);

    const float AC = 0.1f, OMA = 0.9f;
    float* ex = (float*)(sm + B_OFF);      // [128][68] exchange, aliases B

    for (int t = 0; t < TT; ++t) {
        const float* __restrict__ cur = g_h[t & 1];
        float* __restrict__ nxt = g_h[(t + 1) & 1];

        // ---- phase 1: B-copy (single fp16 plane) in 2 committed chunks ----
        const char* src = inp ? (const char*)&g_x16[(size_t)t * II * BB]
                              : (const char*)&g_r16[(size_t)k0 * BB];
        const int half_rows = inp ? 64 : 128;   // rows per wk half
        const int crows = half_rows >> 1;       // rows per chunk
        const int row0 = wk * half_rows;
#pragma unroll
        for (int ch = 0; ch < 2; ++ch) {
            const int r0c = row0 + ch * crows;
            for (int s = wg_tid; s < crows * 8; s += 128) {
                int r = r0c + (s >> 3), c16 = (s & 7) * 16;
                cp16(smb + B_OFF + r * B_STRIDE + c16, src + r * 128 + c16);
            }
            cp_commit();
        }

        // ---- phase 2: 1-term fp16 MMA, chunk 0 overlapped with chunk-1 arrival ----
        float acc[4][4][4];
#pragma unroll
        for (int a = 0; a < 4; ++a)
#pragma unroll
            for (int b = 0; b < 4; ++b)
#pragma unroll
                for (int q = 0; q < 4; ++q) acc[a][b][q] = 0.0f;

        cp_waitg1();
        named_bar(1 + wk);

#pragma unroll
        for (int half = 0; half < 2; ++half) {
#pragma unroll 2
            for (int j = half * KH; j < half * KH + KH; ++j) {
                const int kk = kkbase + j;
                uint32_t af[4][4];
                const uint32_t aA = aBase + (uint32_t)kk * 32;
#pragma unroll
                for (int mt = 0; mt < 4; ++mt)
                    ldsm4(af[mt], aA + mt * 16 * A_STRIDE);
                uint32_t bf[4][2];
                const uint32_t bA = bBase + (uint32_t)kk * 16 * B_STRIDE;
                ldsm4t(&bf[0][0], bA);
                ldsm4t(&bf[2][0], bA + 32);
#pragma unroll
                for (int mt = 0; mt < 4; ++mt)
#pragma unroll
                    for (int nb = 0; nb < 4; ++nb)
                        mma16816(acc[mt][nb], af[mt], bf[nb]);
            }
            if (half == 0) {
                cp_waitg0();
                named_bar(1 + wk);
            }
        }

        // ---- phase 3: wk-pair combine in smem, then store slice ks ----
        __syncthreads();                   // all B-frag reads complete
        if (wk == 1) {
#pragma unroll
            for (int mt = 0; mt < 4; ++mt)
#pragma unroll
                for (int nb = 0; nb < 4; ++nb)
                    *(float4*)&ex[wg_tid * 68 + (mt * 4 + nb) * 4] =
                        make_float4(acc[mt][nb][0], acc[mt][nb][1],
                                    acc[mt][nb][2], acc[mt][nb][3]);
        }
        __syncthreads();
        if (wk == 0) {
            float* dst = &g_partial[ks][0];
            const int gi = lane >> 2;
            const int ti = lane & 3;
#pragma unroll
            for (int mt = 0; mt < 4; ++mt) {
                int r0 = n0 + wm * 64 + mt * 16 + gi;
#pragma unroll
                for (int nb = 0; nb < 4; ++nb) {
                    float4 o = *(float4*)&ex[wg_tid * 68 + (mt * 4 + nb) * 4];
                    int cb = wb * 32 + nb * 8 + 2 * ti;
                    __stcg((float2*)&dst[(size_t)r0 * BB + cb],
                           make_float2(acc[mt][nb][0] + o.x, acc[mt][nb][1] + o.y));
                    __stcg((float2*)&dst[(size_t)(r0 + 8) * BB + cb],
                           make_float2(acc[mt][nb][2] + o.z, acc[mt][nb][3] + o.w));
                }
            }
        }

        // ---- barrier 1: partials visible ----
        bar += GRID;
        __syncthreads();
        if (tid == 0) { sig_add(&g_arrive, 1u); poll_ge(&g_arrive, bar); }
        __syncthreads();

        // ---- phase 4: distributed reduce + update + relu + publish r ----
        for (int u = tid; u < Rrows * 16; u += NTHREADS) {
            int row = u >> 4;
            int b0 = (u & 15) * 4;
            int n = nbase + row;
            size_t off = (size_t)n * BB + b0;

            float4 s = make_float4(0.f, 0.f, 0.f, 0.f);
#pragma unroll
            for (int p = 0; p < NSL; ++p) {
                float4 q = __ldcg((const float4*)&g_partial[p][off]);
                s.x += q.x; s.y += q.y; s.z += q.z; s.w += q.w;
            }
            float tn = __ldg(&tonic[n]);
            float4 hv = __ldcg((const float4*)&cur[off]);
            float4 r4;
            r4.x = OMA * hv.x + AC * (s.x + tn);
            r4.y = OMA * hv.y + AC * (s.y + tn);
            r4.z = OMA * hv.z + AC * (s.z + tn);
            r4.w = OMA * hv.w + AC * (s.w + tn);
            __stcg((float4*)&nxt[off], r4);

            float rr[4] = {fmaxf(r4.x, 0.f), fmaxf(r4.y, 0.f),
                           fmaxf(r4.z, 0.f), fmaxf(r4.w, 0.f)};
            sm_out[b0 + 0][row] = rr[0];
            sm_out[b0 + 1][row] = rr[1];
            sm_out[b0 + 2][row] = rr[2];
            sm_out[b0 + 3][row] = rr[3];

            __half2 r01 = __floats2half2_rn(rr[0], rr[1]);
            __half2 r23 = __floats2half2_rn(rr[2], rr[3]);
            uint2 pk;
            pk.x = *(uint32_t*)&r01;
            pk.y = *(uint32_t*)&r23;
            *(uint2*)&g_r16[off] = pk;
        }

        // ---- barrier 2 with out-writes overlapped into the wait ----
        bar += GRID;
        __syncthreads();
        if (tid == 0) sig_add(&g_arrive, 1u);
        for (int idx = tid; idx < Rrows * 64; idx += NTHREADS) {
            int b = idx / Rrows;
            int rr2 = idx - b * Rrows;
            out[((size_t)b * TT + t) * NN + nbase + rr2] = sm_out[b][rr2];
        }
        if (tid == 0) poll_ge(&g_arrive, bar);
        __syncthreads();
    }
}

// ---------------- launch ----------------
extern "C" void kernel_launch(void* const* d_in, const int* in_sizes, int n_in,
                              void* d_out, int out_size) {
    const float* x     = (const float*)d_in[0];
    const float* h0    = (const float*)d_in[1];
    const float* Wrec  = (const float*)d_in[2];
    const float* Winp  = (const float*)d_in[3];
    const float* tonic = (const float*)d_in[4];
    const int*   mask  = (const int*)d_in[5];
    const int*   sgn   = (const int*)d_in[6];
    float* out = (float*)d_out;

    cudaFuncSetAttribute(rnn_persistent,
                         cudaFuncAttributeMaxDynamicSharedMemorySize, SMEM_DYN);

    void* pa = nullptr;
    cudaGetSymbolAddress(&pa, g_arrive);
    cudaMemsetAsync(pa, 0, sizeof(unsigned int));

    rnn_persistent<<<GRID, NTHREADS, SMEM_DYN>>>(x, h0, Wrec, Winp, tonic,
                                                 mask, sgn, out);
}